// round 6
// baseline (speedup 1.0000x reference)
#include <cuda_runtime.h>
#include <cuda_fp16.h>
#include <cstdint>

// Problem constants (B=4, T=4096, C=1024, H=16, D=64, BLOCK=128)
#define B_    4
#define T_    4096
#define C_    1024
#define H_    16
#define Dh_   64
#define BS_   128
#define M_TOK 16384
#define N_QKV 3072
#define KDIM  1024

// Scratch (allocation-free rule: __device__ globals)
__device__ __half g_qkvh  [(size_t)M_TOK * N_QKV];  // 96 MiB
__device__ __half g_attnh [(size_t)M_TOK * C_];     // 32 MiB
__device__ __half g_xh    [(size_t)M_TOK * C_];     // 32 MiB
__device__ __half g_WqkvT [(size_t)N_QKV * KDIM];   // 6 MiB  [N][K]
__device__ __half g_WprojT[(size_t)C_ * KDIM];      // 2 MiB  [N][K]

// ---------------------------------------------------------------------------
// helpers
// ---------------------------------------------------------------------------
__device__ __forceinline__ uint32_t smem_u32(const void* p) {
    uint32_t a;
    asm("{ .reg .u64 t; cvta.to.shared.u64 t, %1; cvt.u32.u64 %0, t; }" : "=r"(a) : "l"(p));
    return a;
}
// D += A*B, m16n8k16 f16 inputs, f32 accum
__device__ __forceinline__ void mma_f16(float* d, const uint32_t* a, const uint32_t* b) {
    asm volatile(
        "mma.sync.aligned.m16n8k16.row.col.f32.f16.f16.f32 "
        "{%0,%1,%2,%3}, {%4,%5,%6,%7}, {%8,%9}, {%0,%1,%2,%3};"
        : "+f"(d[0]), "+f"(d[1]), "+f"(d[2]), "+f"(d[3])
        : "r"(a[0]), "r"(a[1]), "r"(a[2]), "r"(a[3]), "r"(b[0]), "r"(b[1]));
}
#define LDSM4(r0, r1, r2, r3, addr) \
    asm volatile("ldmatrix.sync.aligned.m8n8.x4.shared.b16 {%0,%1,%2,%3}, [%4];" \
                 : "=r"(r0), "=r"(r1), "=r"(r2), "=r"(r3) : "r"(addr))
#define LDSM4T(r0, r1, r2, r3, addr) \
    asm volatile("ldmatrix.sync.aligned.m8n8.x4.trans.shared.b16 {%0,%1,%2,%3}, [%4];" \
                 : "=r"(r0), "=r"(r1), "=r"(r2), "=r"(r3) : "r"(addr))
#define CP16(dst, src) \
    asm volatile("cp.async.cg.shared.global [%0], [%1], 16;" :: "r"(dst), "l"(src))
#define CP_COMMIT() asm volatile("cp.async.commit_group;")
#define CP_WAIT2()  asm volatile("cp.async.wait_group 2;")

// ---------------------------------------------------------------------------
// conversion kernels
// ---------------------------------------------------------------------------
__global__ void cvt_f2h(const float4* __restrict__ in, uint2* __restrict__ out, int n4) {
    int i = blockIdx.x * blockDim.x + threadIdx.x;
    if (i < n4) {
        float4 v = in[i];
        __half2 h0 = __floats2half2_rn(v.x, v.y);
        __half2 h1 = __floats2half2_rn(v.z, v.w);
        out[i] = make_uint2(*(uint32_t*)&h0, *(uint32_t*)&h1);
    }
}
// in fp32 [R][Cc] -> out half [Cc][R]
__global__ void transpose_cvt(const float* __restrict__ in, __half* __restrict__ out,
                              int R, int Cc)
{
    __shared__ float t[32][33];
    int x = blockIdx.x * 32 + threadIdx.x;
    int y = blockIdx.y * 32 + threadIdx.y;
#pragma unroll
    for (int j = 0; j < 32; j += 8)
        t[threadIdx.y + j][threadIdx.x] = in[(size_t)(y + j) * Cc + x];
    __syncthreads();
    int x2 = blockIdx.y * 32 + threadIdx.x;
    int y2 = blockIdx.x * 32 + threadIdx.y;
#pragma unroll
    for (int j = 0; j < 32; j += 8)
        out[(size_t)(y2 + j) * R + x2] = __float2half(t[threadIdx.x][threadIdx.y + j]);
}

// ---------------------------------------------------------------------------
// fp16 mma GEMM: C[M,N] = A[M,1024] @ Bt[N,1024]^T (+bias).
// A half [M][K], Bt half [N][K]. 256x128 CTA tiles, BK=64 halves, 4-stage
// cp.async pipeline, 8 warps (4x2), 64x64 warp tile, ldmatrix fragment loads.
// ---------------------------------------------------------------------------
#define GP2      72                         // smem pitch (halves), 144B rows
#define A_ROWS   256
#define B_ROWS   128
#define ASTG2_H  (A_ROWS * GP2)             // 18432 halves
#define BSTG2_H  (B_ROWS * GP2)             // 9216 halves
#define STG2_B   ((ASTG2_H + BSTG2_H) * 2)  // 55296 bytes per stage
#define GSMEM_B  (4 * STG2_B)               // 221184 bytes

template <bool BIAS, bool HALF_OUT>
__global__ __launch_bounds__(256, 1)
void gemm_h(const __half* __restrict__ A, const __half* __restrict__ Bt,
            const float* __restrict__ bias, void* __restrict__ Cout, int N)
{
    extern __shared__ __half smh[];
    const uint32_t sb = smem_u32(smh);
    const int tid = threadIdx.x, lane = tid & 31, wid = tid >> 5;
    const int wm = wid >> 1, wn = wid & 1, gr = lane >> 2, ctg = lane & 3;
    const int bm = blockIdx.y * 256, bn = blockIdx.x * 128;

    auto load_tile = [&](int s, int k0) {
        uint32_t sA = sb + (uint32_t)(s * STG2_B);
        uint32_t sB = sA + ASTG2_H * 2;
#pragma unroll
        for (int i = 0; i < 8; i++) {              // A: 256 rows x 64 halves
            int ch = tid + i * 256;
            int r = ch >> 3, kc = (ch & 7) << 3;
            CP16(sA + (uint32_t)(r * GP2 + kc) * 2,
                 A + (size_t)(bm + r) * KDIM + k0 + kc);
        }
#pragma unroll
        for (int i = 0; i < 4; i++) {              // B: 128 rows x 64 halves
            int ch = tid + i * 256;
            int r = ch >> 3, kc = (ch & 7) << 3;
            CP16(sB + (uint32_t)(r * GP2 + kc) * 2,
                 Bt + (size_t)(bn + r) * KDIM + k0 + kc);
        }
    };

    // ldmatrix per-lane base offsets (bytes)
    const uint32_t aOff = (uint32_t)((wm * 64 + (lane & 15)) * GP2 + ((lane >> 4) << 3)) * 2;
    const uint32_t bOff = (uint32_t)((wn * 64 + ((lane & 16) >> 1) + (lane & 7)) * GP2
                                     + ((lane & 8) ? 8 : 0)) * 2;

    load_tile(0, 0);   CP_COMMIT();
    load_tile(1, 64);  CP_COMMIT();
    load_tile(2, 128); CP_COMMIT();

    float acc[4][8][4] = {};

    for (int it = 0; it < 16; ++it) {
        const int s = it & 3;
        CP_WAIT2();
        __syncthreads();
        if (it + 3 < 16) load_tile((it + 3) & 3, (it + 3) * 64);
        CP_COMMIT();

        const uint32_t sA = sb + (uint32_t)(s * STG2_B);
        const uint32_t sB = sA + ASTG2_H * 2;
#pragma unroll
        for (int kk = 0; kk < 4; ++kk) {
            const uint32_t kbB = (uint32_t)(kk * 16) * 2;
            uint32_t a[4][4], bfr[8][2];
#pragma unroll
            for (int mi = 0; mi < 4; ++mi)
                LDSM4(a[mi][0], a[mi][1], a[mi][2], a[mi][3],
                      sA + aOff + (uint32_t)(mi * 16 * GP2) * 2 + kbB);
#pragma unroll
            for (int pn = 0; pn < 4; ++pn)
                LDSM4(bfr[2 * pn][0], bfr[2 * pn][1], bfr[2 * pn + 1][0], bfr[2 * pn + 1][1],
                      sB + bOff + (uint32_t)(pn * 16 * GP2) * 2 + kbB);
#pragma unroll
            for (int mi = 0; mi < 4; ++mi)
#pragma unroll
                for (int ni = 0; ni < 8; ++ni)
                    mma_f16(acc[mi][ni], a[mi], bfr[ni]);
        }
    }

    // epilogue: c-frag rows gr, gr+8; cols 2ctg, 2ctg+1
#pragma unroll
    for (int mi = 0; mi < 4; mi++) {
        int r0 = bm + wm * 64 + mi * 16 + gr;
#pragma unroll
        for (int ni = 0; ni < 8; ni++) {
            int c0 = bn + wn * 64 + ni * 8 + 2 * ctg;
            if (HALF_OUT) {
                __half* C = (__half*)Cout;
                __half2 v0 = __floats2half2_rn(acc[mi][ni][0], acc[mi][ni][1]);
                __half2 v1 = __floats2half2_rn(acc[mi][ni][2], acc[mi][ni][3]);
                *(__half2*)&C[(size_t)r0 * N + c0]       = v0;
                *(__half2*)&C[(size_t)(r0 + 8) * N + c0] = v1;
            } else {
                float* C = (float*)Cout;
                float bx = 0.f, by = 0.f;
                if (BIAS) { bx = bias[c0]; by = bias[c0 + 1]; }
                float2 v0 = make_float2(acc[mi][ni][0] + bx, acc[mi][ni][1] + by);
                float2 v1 = make_float2(acc[mi][ni][2] + bx, acc[mi][ni][3] + by);
                *(float2*)&C[(size_t)r0 * N + c0]       = v0;
                *(float2*)&C[(size_t)(r0 + 8) * N + c0] = v1;
            }
        }
    }
}

// ---------------------------------------------------------------------------
// Block-local causal attention, fp16 mma + ldmatrix. grid = (H, T/128, B),
// 256 threads. Reads fp16 qkv, writes fp16 attn output. (unchanged from R5)
// ---------------------------------------------------------------------------
#define QPH 72
#define PPH 136
#define OFF_Q 0
#define OFF_K (128 * QPH)
#define OFF_P (2 * 128 * QPH)
#define OFF_RED_B ((OFF_P + 128 * PPH) * 2)
#define ATT_B (OFF_RED_B + 128 * 4 * 4)

__global__ __launch_bounds__(256, 1)
void attn_h(const __half* __restrict__ qkv, __half* __restrict__ outp)
{
    extern __shared__ __half smh[];
    const uint32_t sbA = smem_u32(smh);
    const int h = blockIdx.x, blk = blockIdx.y, b = blockIdx.z;
    const int token0 = b * T_ + blk * BS_;
    const __half* qp = qkv + (size_t)token0 * N_QKV + h * Dh_;
    const __half* kp = qp + C_;
    const __half* vp = qp + 2 * C_;

    const int tid = threadIdx.x, lane = tid & 31, wid = tid >> 5;
    const int wm = wid >> 2, wn = wid & 3, gr = lane >> 2, ctg = lane & 3;

    __half* Qs = smh + OFF_Q;
    __half* Ks = smh + OFF_K;
    __half* Vs = smh + OFF_Q;
    __half* Ps = smh + OFF_P;
    float*  red = (float*)((char*)smh + OFF_RED_B);

    const uint32_t uQ = sbA + OFF_Q * 2;
    const uint32_t uK = sbA + OFF_K * 2;
    const uint32_t uV = uQ;
    const uint32_t uP = sbA + OFF_P * 2;

    for (int i = tid; i < 1024; i += 256) {
        int r = i >> 3, c8 = (i & 7) << 3;
        *(uint4*)&Qs[r * QPH + c8] = *(const uint4*)(qp + (size_t)r * N_QKV + c8);
        *(uint4*)&Ks[r * QPH + c8] = *(const uint4*)(kp + (size_t)r * N_QKV + c8);
    }
    __syncthreads();

    const uint32_t aOffQ = (uint32_t)((wm * 64 + (lane & 15)) * QPH + ((lane >> 4) << 3)) * 2;
    const uint32_t bOffK = (uint32_t)((wn * 32 + ((lane & 16) >> 1) + (lane & 7)) * QPH
                                      + ((lane & 8) ? 8 : 0)) * 2;
    const uint32_t aOffP = (uint32_t)((wm * 64 + (lane & 15)) * PPH + ((lane >> 4) << 3)) * 2;
    const uint32_t bOffV = (uint32_t)(((lane & 7) + ((lane & 8) ? 8 : 0)) * QPH
                                      + wn * 16 + ((lane & 16) ? 8 : 0)) * 2;

    float acc[4][4][4] = {};
    const bool liveQK = (wn * 32 <= wm * 64 + 63);
    if (liveQK) {
#pragma unroll
        for (int kk = 0; kk < 4; ++kk) {
            const uint32_t kbB = (uint32_t)(kk * 16) * 2;
            uint32_t a[4][4], bfr[4][2];
#pragma unroll
            for (int mi = 0; mi < 4; ++mi)
                LDSM4(a[mi][0], a[mi][1], a[mi][2], a[mi][3],
                      uQ + aOffQ + (uint32_t)(mi * 16 * QPH) * 2 + kbB);
#pragma unroll
            for (int pn = 0; pn < 2; ++pn)
                LDSM4(bfr[2 * pn][0], bfr[2 * pn][1], bfr[2 * pn + 1][0], bfr[2 * pn + 1][1],
                      uK + bOffK + (uint32_t)(pn * 16 * QPH) * 2 + kbB);
#pragma unroll
            for (int mi = 0; mi < 4; ++mi)
#pragma unroll
                for (int ni = 0; ni < 4; ++ni)
                    mma_f16(acc[mi][ni], a[mi], bfr[ni]);
        }
    }

    float rsum[4][2];
#pragma unroll
    for (int mi = 0; mi < 4; ++mi) { rsum[mi][0] = 0.f; rsum[mi][1] = 0.f; }
#pragma unroll
    for (int mi = 0; mi < 4; ++mi)
#pragma unroll
        for (int ni = 0; ni < 4; ++ni)
#pragma unroll
            for (int e = 0; e < 4; ++e) {
                int row = wm * 64 + mi * 16 + gr + ((e >= 2) ? 8 : 0);
                int col = wn * 32 + ni * 8 + 2 * ctg + (e & 1);
                float v = (col <= row) ? __expf(acc[mi][ni][e] * 0.125f) : 0.f;
                acc[mi][ni][e] = v;
                rsum[mi][e >> 1] += v;
            }
#pragma unroll
    for (int mi = 0; mi < 4; ++mi)
#pragma unroll
        for (int hl = 0; hl < 2; ++hl) {
            float s = rsum[mi][hl];
            s += __shfl_xor_sync(0xffffffffu, s, 1);
            s += __shfl_xor_sync(0xffffffffu, s, 2);
            rsum[mi][hl] = s;
        }
    if (ctg == 0)
#pragma unroll
        for (int mi = 0; mi < 4; ++mi)
#pragma unroll
            for (int hl = 0; hl < 2; ++hl)
                red[(wm * 64 + mi * 16 + gr + hl * 8) * 4 + wn] = rsum[mi][hl];
    __syncthreads();

    for (int i = tid; i < 1024; i += 256) {
        int r = i >> 3, c8 = (i & 7) << 3;
        *(uint4*)&Vs[r * QPH + c8] = *(const uint4*)(vp + (size_t)r * N_QKV + c8);
    }

#pragma unroll
    for (int mi = 0; mi < 4; ++mi)
#pragma unroll
        for (int hl = 0; hl < 2; ++hl) {
            int row = wm * 64 + mi * 16 + gr + hl * 8;
            float ssum = red[row * 4 + 0] + red[row * 4 + 1]
                       + red[row * 4 + 2] + red[row * 4 + 3];
            float inv = __fdividef(1.f, ssum + 1e-6f);
#pragma unroll
            for (int ni = 0; ni < 4; ++ni) {
                __half2 pv = __floats2half2_rn(acc[mi][ni][hl * 2 + 0] * inv,
                                               acc[mi][ni][hl * 2 + 1] * inv);
                *(__half2*)&Ps[row * PPH + wn * 32 + ni * 8 + 2 * ctg] = pv;
            }
        }
    __syncthreads();

    float oa[4][2][4] = {};
#pragma unroll
    for (int kk = 0; kk < 8; ++kk) {
        const uint32_t kbP = (uint32_t)(kk * 16) * 2;
        uint32_t a[4][4], bfr[2][2];
#pragma unroll
        for (int mi = 0; mi < 4; ++mi)
            LDSM4(a[mi][0], a[mi][1], a[mi][2], a[mi][3],
                  uP + aOffP + (uint32_t)(mi * 16 * PPH) * 2 + kbP);
        LDSM4T(bfr[0][0], bfr[0][1], bfr[1][0], bfr[1][1],
               uV + bOffV + (uint32_t)(kk * 16 * QPH) * 2);
#pragma unroll
        for (int mi = 0; mi < 4; ++mi)
#pragma unroll
            for (int ni = 0; ni < 2; ++ni)
                mma_f16(oa[mi][ni], a[mi], bfr[ni]);
    }

    __half* op = outp + (size_t)token0 * C_ + h * Dh_;
#pragma unroll
    for (int mi = 0; mi < 4; ++mi) {
        int r0 = wm * 64 + mi * 16 + gr;
#pragma unroll
        for (int ni = 0; ni < 2; ++ni) {
            int c0 = wn * 16 + ni * 8 + 2 * ctg;
            __half2 v0 = __floats2half2_rn(oa[mi][ni][0], oa[mi][ni][1]);
            __half2 v1 = __floats2half2_rn(oa[mi][ni][2], oa[mi][ni][3]);
            *(__half2*)&op[(size_t)r0 * C_ + c0]       = v0;
            *(__half2*)&op[(size_t)(r0 + 8) * C_ + c0] = v1;
        }
    }
}

// ---------------------------------------------------------------------------
extern "C" void kernel_launch(void* const* d_in, const int* in_sizes, int n_in,
                              void* d_out, int out_size)
{
    const float* x      = (const float*)d_in[0];
    const float* W_qkv  = (const float*)d_in[1];
    const float* W_proj = (const float*)d_in[2];
    const float* b_proj = (const float*)d_in[3];
    float* out = (float*)d_out;

    __half *qkvh, *attnh, *xh, *WqkvT, *WprojT;
    cudaGetSymbolAddress((void**)&qkvh,   g_qkvh);
    cudaGetSymbolAddress((void**)&attnh,  g_attnh);
    cudaGetSymbolAddress((void**)&xh,     g_xh);
    cudaGetSymbolAddress((void**)&WqkvT,  g_WqkvT);
    cudaGetSymbolAddress((void**)&WprojT, g_WprojT);

    static bool attr_set = false;
    if (!attr_set) {
        cudaFuncSetAttribute((const void*)gemm_h<false, true>,
                             cudaFuncAttributeMaxDynamicSharedMemorySize, GSMEM_B);
        cudaFuncSetAttribute((const void*)gemm_h<true, false>,
                             cudaFuncAttributeMaxDynamicSharedMemorySize, GSMEM_B);
        cudaFuncSetAttribute((const void*)attn_h,
                             cudaFuncAttributeMaxDynamicSharedMemorySize, ATT_B);
        attr_set = true;
    }

    // 0) fp16 conversions
    cvt_f2h<<<(M_TOK * C_ / 4 + 255) / 256, 256>>>((const float4*)x, (uint2*)xh,
                                                   M_TOK * C_ / 4);
    transpose_cvt<<<dim3(N_QKV / 32, KDIM / 32), dim3(32, 8)>>>(W_qkv, WqkvT, KDIM, N_QKV);
    transpose_cvt<<<dim3(C_ / 32, KDIM / 32), dim3(32, 8)>>>(W_proj, WprojT, KDIM, C_);

    // 1) qkv = x @ W_qkv  (fp16 mma, fp16 out)
    gemm_h<false, true><<<dim3(N_QKV / 128, M_TOK / 256), 256, GSMEM_B>>>(
        xh, WqkvT, nullptr, qkvh, N_QKV);

    // 2) block-local causal attention (fp16 mma)
    attn_h<<<dim3(H_, T_ / BS_, B_), 256, ATT_B>>>(qkvh, attnh);

    // 3) out = attn @ W_proj + b_proj (fp16 mma, fp32 out)
    gemm_h<true, false><<<dim3(C_ / 128, M_TOK / 256), 256, GSMEM_B>>>(
        attnh, WprojT, b_proj, out, C_);
}

// round 7
// speedup vs baseline: 1.2293x; 1.2293x over previous
#include <cuda_runtime.h>
#include <cuda_fp16.h>
#include <cstdint>

// Problem constants (B=4, T=4096, C=1024, H=16, D=64, BLOCK=128)
#define B_    4
#define T_    4096
#define C_    1024
#define H_    16
#define Dh_   64
#define BS_   128
#define M_TOK 16384
#define N_QKV 3072
#define KDIM  1024

// Scratch (allocation-free rule: __device__ globals)
__device__ __half g_qkvh  [(size_t)M_TOK * N_QKV];  // 96 MiB
__device__ __half g_attnh [(size_t)M_TOK * C_];     // 32 MiB
__device__ __half g_xh    [(size_t)M_TOK * C_];     // 32 MiB
__device__ __half g_WqkvT [(size_t)N_QKV * KDIM];   // 6 MiB  [N][K]
__device__ __half g_WprojT[(size_t)C_ * KDIM];      // 2 MiB  [N][K]

// ---------------------------------------------------------------------------
// helpers
// ---------------------------------------------------------------------------
__device__ __forceinline__ uint32_t smem_u32(const void* p) {
    uint32_t a;
    asm("{ .reg .u64 t; cvta.to.shared.u64 t, %1; cvt.u32.u64 %0, t; }" : "=r"(a) : "l"(p));
    return a;
}
// D += A*B, m16n8k16 f16 inputs, f32 accum
__device__ __forceinline__ void mma_f16(float* d, const uint32_t* a, const uint32_t* b) {
    asm volatile(
        "mma.sync.aligned.m16n8k16.row.col.f32.f16.f16.f32 "
        "{%0,%1,%2,%3}, {%4,%5,%6,%7}, {%8,%9}, {%0,%1,%2,%3};"
        : "+f"(d[0]), "+f"(d[1]), "+f"(d[2]), "+f"(d[3])
        : "r"(a[0]), "r"(a[1]), "r"(a[2]), "r"(a[3]), "r"(b[0]), "r"(b[1]));
}
#define LDSM4(r0, r1, r2, r3, addr) \
    asm volatile("ldmatrix.sync.aligned.m8n8.x4.shared.b16 {%0,%1,%2,%3}, [%4];" \
                 : "=r"(r0), "=r"(r1), "=r"(r2), "=r"(r3) : "r"(addr))
#define LDSM4T(r0, r1, r2, r3, addr) \
    asm volatile("ldmatrix.sync.aligned.m8n8.x4.trans.shared.b16 {%0,%1,%2,%3}, [%4];" \
                 : "=r"(r0), "=r"(r1), "=r"(r2), "=r"(r3) : "r"(addr))
#define CP16(dst, src) \
    asm volatile("cp.async.cg.shared.global [%0], [%1], 16;" :: "r"(dst), "l"(src))
#define CP_COMMIT() asm volatile("cp.async.commit_group;")
#define CP_WAIT1()  asm volatile("cp.async.wait_group 1;")

// ---------------------------------------------------------------------------
// conversion kernels
// ---------------------------------------------------------------------------
__global__ void cvt_f2h(const float4* __restrict__ in, uint2* __restrict__ out, int n4) {
    int i = blockIdx.x * blockDim.x + threadIdx.x;
    if (i < n4) {
        float4 v = in[i];
        __half2 h0 = __floats2half2_rn(v.x, v.y);
        __half2 h1 = __floats2half2_rn(v.z, v.w);
        out[i] = make_uint2(*(uint32_t*)&h0, *(uint32_t*)&h1);
    }
}
// in fp32 [R][Cc] -> out half [Cc][R]
__global__ void transpose_cvt(const float* __restrict__ in, __half* __restrict__ out,
                              int R, int Cc)
{
    __shared__ float t[32][33];
    int x = blockIdx.x * 32 + threadIdx.x;
    int y = blockIdx.y * 32 + threadIdx.y;
#pragma unroll
    for (int j = 0; j < 32; j += 8)
        t[threadIdx.y + j][threadIdx.x] = in[(size_t)(y + j) * Cc + x];
    __syncthreads();
    int x2 = blockIdx.y * 32 + threadIdx.x;
    int y2 = blockIdx.x * 32 + threadIdx.y;
#pragma unroll
    for (int j = 0; j < 32; j += 8)
        out[(size_t)(y2 + j) * R + x2] = __float2half(t[threadIdx.x][threadIdx.y + j]);
}

// ---------------------------------------------------------------------------
// fp16 mma GEMM: C[M,N] = A[M,1024] @ Bt[N,1024]^T (+bias).
// A half [M][K], Bt half [N][K]. 128x128 CTA tiles, BK=64 halves, 3-stage
// cp.async pipeline, 8 warps (2x4), 64x32 warp tile, ldmatrix fragment loads.
// SMEM: exact 128B rows with 16B-granule XOR swizzle g' = g ^ (row & 7).
// Row = one cache line -> conflict-free cp.async fills AND conflict-free LDSM.
// ---------------------------------------------------------------------------
#define ROWB     128                        // bytes per smem row (64 halves)
#define ASTG_B   (128 * ROWB)               // 16384 bytes per operand tile
#define STG_B    (2 * ASTG_B)               // 32768 bytes per stage (A + B)
#define GSMEM_B  (3 * STG_B)                // 98304 bytes

__device__ __forceinline__ uint32_t swz(uint32_t row, uint32_t g) {
    return row * ROWB + (((g ^ (row & 7)) & 7) << 4);
}

template <bool BIAS, bool HALF_OUT>
__global__ __launch_bounds__(256, 2)
void gemm_h(const __half* __restrict__ A, const __half* __restrict__ Bt,
            const float* __restrict__ bias, void* __restrict__ Cout, int N)
{
    extern __shared__ __half smh[];
    const uint32_t sb = smem_u32(smh);
    const int tid = threadIdx.x, lane = tid & 31, wid = tid >> 5;
    const int wm = wid >> 2, wn = wid & 3, gr = lane >> 2, ctg = lane & 3;
    const int bm = blockIdx.y * 128, bn = blockIdx.x * 128;

    // tile fill: thread handles (row = ch>>3, granule = ch&7)
    auto load_tile = [&](int s, int k0) {
        uint32_t sA = sb + (uint32_t)(s * STG_B);
        uint32_t sB = sA + ASTG_B;
#pragma unroll
        for (int i = 0; i < 4; i++) {              // A: 128 rows x 8 granules
            int ch = tid + i * 256;
            uint32_t r = ch >> 3, g = ch & 7;
            CP16(sA + swz(r, g), A + (size_t)(bm + r) * KDIM + k0 + g * 8);
        }
#pragma unroll
        for (int i = 0; i < 4; i++) {              // B: 128 rows x 8 granules
            int ch = tid + i * 256;
            uint32_t r = ch >> 3, g = ch & 7;
            CP16(sB + swz(r, g), Bt + (size_t)(bn + r) * KDIM + k0 + g * 8);
        }
    };

    // ldmatrix lane roles
    const uint32_t rA  = (uint32_t)(wm * 64 + (lane & 15));   // A row (mi adds 16)
    const uint32_t gA0 = (uint32_t)(lane >> 4);               // A granule lsb
    const uint32_t rB  = (uint32_t)(wn * 32 + ((lane & 16) >> 1) + (lane & 7)); // B row (pn adds 16)
    const uint32_t gB0 = (uint32_t)((lane & 8) >> 3);         // B granule lsb

    load_tile(0, 0);  CP_COMMIT();
    load_tile(1, 64); CP_COMMIT();

    float acc[4][4][4] = {};

    for (int it = 0; it < 16; ++it) {
        const int s = it % 3;
        CP_WAIT1();
        __syncthreads();
        if (it + 2 < 16) load_tile((it + 2) % 3, (it + 2) * 64);
        CP_COMMIT();

        const uint32_t sA = sb + (uint32_t)(s * STG_B);
        const uint32_t sB = sA + ASTG_B;
#pragma unroll
        for (int kk = 0; kk < 4; ++kk) {
            const uint32_t gA = 2 * kk + gA0;     // granule for this kstep
            const uint32_t gB = 2 * kk + gB0;
            uint32_t a[4][4], bfr[4][2];
#pragma unroll
            for (int mi = 0; mi < 4; ++mi)
                LDSM4(a[mi][0], a[mi][1], a[mi][2], a[mi][3],
                      sA + swz(rA + mi * 16, gA));
#pragma unroll
            for (int pn = 0; pn < 2; ++pn)
                LDSM4(bfr[2 * pn][0], bfr[2 * pn][1], bfr[2 * pn + 1][0], bfr[2 * pn + 1][1],
                      sB + swz(rB + pn * 16, gB));
#pragma unroll
            for (int mi = 0; mi < 4; ++mi)
#pragma unroll
                for (int ni = 0; ni < 4; ++ni)
                    mma_f16(acc[mi][ni], a[mi], bfr[ni]);
        }
    }

    // epilogue: c-frag rows gr, gr+8; cols 2ctg, 2ctg+1
#pragma unroll
    for (int mi = 0; mi < 4; mi++) {
        int r0 = bm + wm * 64 + mi * 16 + gr;
#pragma unroll
        for (int ni = 0; ni < 4; ni++) {
            int c0 = bn + wn * 32 + ni * 8 + 2 * ctg;
            if (HALF_OUT) {
                __half* C = (__half*)Cout;
                __half2 v0 = __floats2half2_rn(acc[mi][ni][0], acc[mi][ni][1]);
                __half2 v1 = __floats2half2_rn(acc[mi][ni][2], acc[mi][ni][3]);
                *(__half2*)&C[(size_t)r0 * N + c0]       = v0;
                *(__half2*)&C[(size_t)(r0 + 8) * N + c0] = v1;
            } else {
                float* C = (float*)Cout;
                float bx = 0.f, by = 0.f;
                if (BIAS) { bx = bias[c0]; by = bias[c0 + 1]; }
                float2 v0 = make_float2(acc[mi][ni][0] + bx, acc[mi][ni][1] + by);
                float2 v1 = make_float2(acc[mi][ni][2] + bx, acc[mi][ni][3] + by);
                *(float2*)&C[(size_t)r0 * N + c0]       = v0;
                *(float2*)&C[(size_t)(r0 + 8) * N + c0] = v1;
            }
        }
    }
}

// ---------------------------------------------------------------------------
// Block-local causal attention, fp16 mma + ldmatrix (verbatim from R5, passed).
// grid = (H, T/128, B), 256 threads.
// ---------------------------------------------------------------------------
#define QPH 72
#define PPH 136
#define OFF_Q 0
#define OFF_K (128 * QPH)
#define OFF_P (2 * 128 * QPH)
#define OFF_RED_B ((OFF_P + 128 * PPH) * 2)
#define ATT_B (OFF_RED_B + 128 * 4 * 4)

__global__ __launch_bounds__(256, 1)
void attn_h(const __half* __restrict__ qkv, __half* __restrict__ outp)
{
    extern __shared__ __half smh[];
    const uint32_t sbA = smem_u32(smh);
    const int h = blockIdx.x, blk = blockIdx.y, b = blockIdx.z;
    const int token0 = b * T_ + blk * BS_;
    const __half* qp = qkv + (size_t)token0 * N_QKV + h * Dh_;
    const __half* kp = qp + C_;
    const __half* vp = qp + 2 * C_;

    const int tid = threadIdx.x, lane = tid & 31, wid = tid >> 5;
    const int wm = wid >> 2, wn = wid & 3, gr = lane >> 2, ctg = lane & 3;

    __half* Qs = smh + OFF_Q;
    __half* Ks = smh + OFF_K;
    __half* Vs = smh + OFF_Q;
    __half* Ps = smh + OFF_P;
    float*  red = (float*)((char*)smh + OFF_RED_B);

    const uint32_t uQ = sbA + OFF_Q * 2;
    const uint32_t uK = sbA + OFF_K * 2;
    const uint32_t uV = uQ;
    const uint32_t uP = sbA + OFF_P * 2;

    for (int i = tid; i < 1024; i += 256) {
        int r = i >> 3, c8 = (i & 7) << 3;
        *(uint4*)&Qs[r * QPH + c8] = *(const uint4*)(qp + (size_t)r * N_QKV + c8);
        *(uint4*)&Ks[r * QPH + c8] = *(const uint4*)(kp + (size_t)r * N_QKV + c8);
    }
    __syncthreads();

    const uint32_t aOffQ = (uint32_t)((wm * 64 + (lane & 15)) * QPH + ((lane >> 4) << 3)) * 2;
    const uint32_t bOffK = (uint32_t)((wn * 32 + ((lane & 16) >> 1) + (lane & 7)) * QPH
                                      + ((lane & 8) ? 8 : 0)) * 2;
    const uint32_t aOffP = (uint32_t)((wm * 64 + (lane & 15)) * PPH + ((lane >> 4) << 3)) * 2;
    const uint32_t bOffV = (uint32_t)(((lane & 7) + ((lane & 8) ? 8 : 0)) * QPH
                                      + wn * 16 + ((lane & 16) ? 8 : 0)) * 2;

    float acc[4][4][4] = {};
    const bool liveQK = (wn * 32 <= wm * 64 + 63);
    if (liveQK) {
#pragma unroll
        for (int kk = 0; kk < 4; ++kk) {
            const uint32_t kbB = (uint32_t)(kk * 16) * 2;
            uint32_t a[4][4], bfr[4][2];
#pragma unroll
            for (int mi = 0; mi < 4; ++mi)
                LDSM4(a[mi][0], a[mi][1], a[mi][2], a[mi][3],
                      uQ + aOffQ + (uint32_t)(mi * 16 * QPH) * 2 + kbB);
#pragma unroll
            for (int pn = 0; pn < 2; ++pn)
                LDSM4(bfr[2 * pn][0], bfr[2 * pn][1], bfr[2 * pn + 1][0], bfr[2 * pn + 1][1],
                      uK + bOffK + (uint32_t)(pn * 16 * QPH) * 2 + kbB);
#pragma unroll
            for (int mi = 0; mi < 4; ++mi)
#pragma unroll
                for (int ni = 0; ni < 4; ++ni)
                    mma_f16(acc[mi][ni], a[mi], bfr[ni]);
        }
    }

    float rsum[4][2];
#pragma unroll
    for (int mi = 0; mi < 4; ++mi) { rsum[mi][0] = 0.f; rsum[mi][1] = 0.f; }
#pragma unroll
    for (int mi = 0; mi < 4; ++mi)
#pragma unroll
        for (int ni = 0; ni < 4; ++ni)
#pragma unroll
            for (int e = 0; e < 4; ++e) {
                int row = wm * 64 + mi * 16 + gr + ((e >= 2) ? 8 : 0);
                int col = wn * 32 + ni * 8 + 2 * ctg + (e & 1);
                float v = (col <= row) ? __expf(acc[mi][ni][e] * 0.125f) : 0.f;
                acc[mi][ni][e] = v;
                rsum[mi][e >> 1] += v;
            }
#pragma unroll
    for (int mi = 0; mi < 4; ++mi)
#pragma unroll
        for (int hl = 0; hl < 2; ++hl) {
            float s = rsum[mi][hl];
            s += __shfl_xor_sync(0xffffffffu, s, 1);
            s += __shfl_xor_sync(0xffffffffu, s, 2);
            rsum[mi][hl] = s;
        }
    if (ctg == 0)
#pragma unroll
        for (int mi = 0; mi < 4; ++mi)
#pragma unroll
            for (int hl = 0; hl < 2; ++hl)
                red[(wm * 64 + mi * 16 + gr + hl * 8) * 4 + wn] = rsum[mi][hl];
    __syncthreads();

    for (int i = tid; i < 1024; i += 256) {
        int r = i >> 3, c8 = (i & 7) << 3;
        *(uint4*)&Vs[r * QPH + c8] = *(const uint4*)(vp + (size_t)r * N_QKV + c8);
    }

#pragma unroll
    for (int mi = 0; mi < 4; ++mi)
#pragma unroll
        for (int hl = 0; hl < 2; ++hl) {
            int row = wm * 64 + mi * 16 + gr + hl * 8;
            float ssum = red[row * 4 + 0] + red[row * 4 + 1]
                       + red[row * 4 + 2] + red[row * 4 + 3];
            float inv = __fdividef(1.f, ssum + 1e-6f);
#pragma unroll
            for (int ni = 0; ni < 4; ++ni) {
                __half2 pv = __floats2half2_rn(acc[mi][ni][hl * 2 + 0] * inv,
                                               acc[mi][ni][hl * 2 + 1] * inv);
                *(__half2*)&Ps[row * PPH + wn * 32 + ni * 8 + 2 * ctg] = pv;
            }
        }
    __syncthreads();

    float oa[4][2][4] = {};
#pragma unroll
    for (int kk = 0; kk < 8; ++kk) {
        const uint32_t kbP = (uint32_t)(kk * 16) * 2;
        uint32_t a[4][4], bfr[2][2];
#pragma unroll
        for (int mi = 0; mi < 4; ++mi)
            LDSM4(a[mi][0], a[mi][1], a[mi][2], a[mi][3],
                  uP + aOffP + (uint32_t)(mi * 16 * PPH) * 2 + kbP);
        LDSM4T(bfr[0][0], bfr[0][1], bfr[1][0], bfr[1][1],
               uV + bOffV + (uint32_t)(kk * 16 * QPH) * 2);
#pragma unroll
        for (int mi = 0; mi < 4; ++mi)
#pragma unroll
            for (int ni = 0; ni < 2; ++ni)
                mma_f16(oa[mi][ni], a[mi], bfr[ni]);
    }

    __half* op = outp + (size_t)token0 * C_ + h * Dh_;
#pragma unroll
    for (int mi = 0; mi < 4; ++mi) {
        int r0 = wm * 64 + mi * 16 + gr;
#pragma unroll
        for (int ni = 0; ni < 2; ++ni) {
            int c0 = wn * 16 + ni * 8 + 2 * ctg;
            __half2 v0 = __floats2half2_rn(oa[mi][ni][0], oa[mi][ni][1]);
            __half2 v1 = __floats2half2_rn(oa[mi][ni][2], oa[mi][ni][3]);
            *(__half2*)&op[(size_t)r0 * C_ + c0]       = v0;
            *(__half2*)&op[(size_t)(r0 + 8) * C_ + c0] = v1;
        }
    }
}

// ---------------------------------------------------------------------------
extern "C" void kernel_launch(void* const* d_in, const int* in_sizes, int n_in,
                              void* d_out, int out_size)
{
    const float* x      = (const float*)d_in[0];
    const float* W_qkv  = (const float*)d_in[1];
    const float* W_proj = (const float*)d_in[2];
    const float* b_proj = (const float*)d_in[3];
    float* out = (float*)d_out;

    __half *qkvh, *attnh, *xh, *WqkvT, *WprojT;
    cudaGetSymbolAddress((void**)&qkvh,   g_qkvh);
    cudaGetSymbolAddress((void**)&attnh,  g_attnh);
    cudaGetSymbolAddress((void**)&xh,     g_xh);
    cudaGetSymbolAddress((void**)&WqkvT,  g_WqkvT);
    cudaGetSymbolAddress((void**)&WprojT, g_WprojT);

    static bool attr_set = false;
    if (!attr_set) {
        cudaFuncSetAttribute((const void*)gemm_h<false, true>,
                             cudaFuncAttributeMaxDynamicSharedMemorySize, GSMEM_B);
        cudaFuncSetAttribute((const void*)gemm_h<true, false>,
                             cudaFuncAttributeMaxDynamicSharedMemorySize, GSMEM_B);
        cudaFuncSetAttribute((const void*)attn_h,
                             cudaFuncAttributeMaxDynamicSharedMemorySize, ATT_B);
        attr_set = true;
    }

    // 0) fp16 conversions
    cvt_f2h<<<(M_TOK * C_ / 4 + 255) / 256, 256>>>((const float4*)x, (uint2*)xh,
                                                   M_TOK * C_ / 4);
    transpose_cvt<<<dim3(N_QKV / 32, KDIM / 32), dim3(32, 8)>>>(W_qkv, WqkvT, KDIM, N_QKV);
    transpose_cvt<<<dim3(C_ / 32, KDIM / 32), dim3(32, 8)>>>(W_proj, WprojT, KDIM, C_);

    // 1) qkv = x @ W_qkv  (fp16 mma, fp16 out)
    gemm_h<false, true><<<dim3(N_QKV / 128, M_TOK / 128), 256, GSMEM_B>>>(
        xh, WqkvT, nullptr, qkvh, N_QKV);

    // 2) block-local causal attention (fp16 mma)
    attn_h<<<dim3(H_, T_ / BS_, B_), 256, ATT_B>>>(qkvh, attnh);

    // 3) out = attn @ W_proj + b_proj (fp16 mma, fp32 out)
    gemm_h<true, false><<<dim3(C_ / 128, M_TOK / 128), 256, GSMEM_B>>>(
        attnh, WprojT, b_proj, out, C_);
}

// round 8
// speedup vs baseline: 1.2348x; 1.0045x over previous
#include <cuda_runtime.h>
#include <cuda_fp16.h>
#include <cstdint>

// Problem constants (B=4, T=4096, C=1024, H=16, D=64, BLOCK=128)
#define B_    4
#define T_    4096
#define C_    1024
#define H_    16
#define Dh_   64
#define BS_   128
#define M_TOK 16384
#define N_QKV 3072
#define KDIM  1024

// Scratch (allocation-free rule: __device__ globals)
__device__ __half g_qkvh  [(size_t)M_TOK * N_QKV];  // 96 MiB
__device__ __half g_attnh [(size_t)M_TOK * C_];     // 32 MiB
__device__ __half g_xh    [(size_t)M_TOK * C_];     // 32 MiB
__device__ __half g_WqkvT [(size_t)N_QKV * KDIM];   // 6 MiB  [N][K]
__device__ __half g_WprojT[(size_t)C_ * KDIM];      // 2 MiB  [N][K]

// ---------------------------------------------------------------------------
// helpers
// ---------------------------------------------------------------------------
__device__ __forceinline__ uint32_t smem_u32(const void* p) {
    uint32_t a;
    asm("{ .reg .u64 t; cvta.to.shared.u64 t, %1; cvt.u32.u64 %0, t; }" : "=r"(a) : "l"(p));
    return a;
}
// D += A*B, m16n8k16 f16 inputs, f32 accum
__device__ __forceinline__ void mma_f16(float* d, const uint32_t* a, const uint32_t* b) {
    asm volatile(
        "mma.sync.aligned.m16n8k16.row.col.f32.f16.f16.f32 "
        "{%0,%1,%2,%3}, {%4,%5,%6,%7}, {%8,%9}, {%0,%1,%2,%3};"
        : "+f"(d[0]), "+f"(d[1]), "+f"(d[2]), "+f"(d[3])
        : "r"(a[0]), "r"(a[1]), "r"(a[2]), "r"(a[3]), "r"(b[0]), "r"(b[1]));
}
#define LDSM4(r0, r1, r2, r3, addr) \
    asm volatile("ldmatrix.sync.aligned.m8n8.x4.shared.b16 {%0,%1,%2,%3}, [%4];" \
                 : "=r"(r0), "=r"(r1), "=r"(r2), "=r"(r3) : "r"(addr))
#define LDSM4T(r0, r1, r2, r3, addr) \
    asm volatile("ldmatrix.sync.aligned.m8n8.x4.trans.shared.b16 {%0,%1,%2,%3}, [%4];" \
                 : "=r"(r0), "=r"(r1), "=r"(r2), "=r"(r3) : "r"(addr))
#define CP16(dst, src) \
    asm volatile("cp.async.cg.shared.global [%0], [%1], 16;" :: "r"(dst), "l"(src))
#define CP_COMMIT() asm volatile("cp.async.commit_group;")
#define CP_WAIT1()  asm volatile("cp.async.wait_group 1;")

// ---------------------------------------------------------------------------
// conversion kernels
// ---------------------------------------------------------------------------
__global__ void cvt_f2h(const float4* __restrict__ in, uint2* __restrict__ out, int n4) {
    int i = blockIdx.x * blockDim.x + threadIdx.x;
    if (i < n4) {
        float4 v = in[i];
        __half2 h0 = __floats2half2_rn(v.x, v.y);
        __half2 h1 = __floats2half2_rn(v.z, v.w);
        out[i] = make_uint2(*(uint32_t*)&h0, *(uint32_t*)&h1);
    }
}
// in fp32 [R][Cc] -> out half [Cc][R]
__global__ void transpose_cvt(const float* __restrict__ in, __half* __restrict__ out,
                              int R, int Cc)
{
    __shared__ float t[32][33];
    int x = blockIdx.x * 32 + threadIdx.x;
    int y = blockIdx.y * 32 + threadIdx.y;
#pragma unroll
    for (int j = 0; j < 32; j += 8)
        t[threadIdx.y + j][threadIdx.x] = in[(size_t)(y + j) * Cc + x];
    __syncthreads();
    int x2 = blockIdx.y * 32 + threadIdx.x;
    int y2 = blockIdx.x * 32 + threadIdx.y;
#pragma unroll
    for (int j = 0; j < 32; j += 8)
        out[(size_t)(y2 + j) * R + x2] = __float2half(t[threadIdx.x][threadIdx.y + j]);
}

// ---------------------------------------------------------------------------
// fp16 mma GEMM: C[M,N] = A[M,1024] @ Bt[N,1024]^T (+bias).
// A half [M][K], Bt half [N][K]. 128x128 CTA tiles, BK=64 halves, 3-stage
// cp.async pipeline, 4 warps (2x2), 64x64 warp tile, ldmatrix fragment loads.
// SMEM: exact 128B rows with 16B-granule XOR swizzle g' = g ^ (row & 7).
// ---------------------------------------------------------------------------
#define ROWB     128                        // bytes per smem row (64 halves)
#define ASTG_B   (128 * ROWB)               // 16384 bytes per operand tile
#define STG_B    (2 * ASTG_B)               // 32768 bytes per stage (A + B)
#define GSMEM_B  (3 * STG_B)                // 98304 bytes

__device__ __forceinline__ uint32_t swz(uint32_t row, uint32_t g) {
    return row * ROWB + (((g ^ (row & 7)) & 7) << 4);
}

template <bool BIAS, bool HALF_OUT>
__global__ __launch_bounds__(128, 2)
void gemm_h(const __half* __restrict__ A, const __half* __restrict__ Bt,
            const float* __restrict__ bias, void* __restrict__ Cout, int N)
{
    extern __shared__ __half smh[];
    const uint32_t sb = smem_u32(smh);
    const int tid = threadIdx.x, lane = tid & 31, wid = tid >> 5;
    const int wm = wid >> 1, wn = wid & 1, gr = lane >> 2, ctg = lane & 3;
    const int bm = blockIdx.y * 128, bn = blockIdx.x * 128;

    // tile fill: thread handles (row = ch>>3, granule = ch&7), 128 threads
    auto load_tile = [&](int s, int k0) {
        uint32_t sA = sb + (uint32_t)(s * STG_B);
        uint32_t sB = sA + ASTG_B;
#pragma unroll
        for (int i = 0; i < 8; i++) {              // A: 128 rows x 8 granules
            int ch = tid + i * 128;
            uint32_t r = ch >> 3, g = ch & 7;
            CP16(sA + swz(r, g), A + (size_t)(bm + r) * KDIM + k0 + g * 8);
        }
#pragma unroll
        for (int i = 0; i < 8; i++) {              // B: 128 rows x 8 granules
            int ch = tid + i * 128;
            uint32_t r = ch >> 3, g = ch & 7;
            CP16(sB + swz(r, g), Bt + (size_t)(bn + r) * KDIM + k0 + g * 8);
        }
    };

    // ldmatrix lane roles
    const uint32_t rA  = (uint32_t)(wm * 64 + (lane & 15));   // A row (mi adds 16)
    const uint32_t gA0 = (uint32_t)(lane >> 4);               // A granule lsb
    const uint32_t rB  = (uint32_t)(wn * 64 + ((lane & 16) >> 1) + (lane & 7)); // B row (pn adds 16)
    const uint32_t gB0 = (uint32_t)((lane & 8) >> 3);         // B granule lsb

    load_tile(0, 0);  CP_COMMIT();
    load_tile(1, 64); CP_COMMIT();

    float acc[4][8][4] = {};

    for (int it = 0; it < 16; ++it) {
        const int s = it % 3;
        CP_WAIT1();
        __syncthreads();
        if (it + 2 < 16) load_tile((it + 2) % 3, (it + 2) * 64);
        CP_COMMIT();

        const uint32_t sA = sb + (uint32_t)(s * STG_B);
        const uint32_t sB = sA + ASTG_B;
#pragma unroll
        for (int kk = 0; kk < 4; ++kk) {
            const uint32_t gA = 2 * kk + gA0;     // granule for this kstep
            const uint32_t gB = 2 * kk + gB0;
            uint32_t a[4][4], bfr[8][2];
#pragma unroll
            for (int mi = 0; mi < 4; ++mi)
                LDSM4(a[mi][0], a[mi][1], a[mi][2], a[mi][3],
                      sA + swz(rA + mi * 16, gA));
#pragma unroll
            for (int pn = 0; pn < 4; ++pn)
                LDSM4(bfr[2 * pn][0], bfr[2 * pn][1], bfr[2 * pn + 1][0], bfr[2 * pn + 1][1],
                      sB + swz(rB + pn * 16, gB));
#pragma unroll
            for (int mi = 0; mi < 4; ++mi)
#pragma unroll
                for (int ni = 0; ni < 8; ++ni)
                    mma_f16(acc[mi][ni], a[mi], bfr[ni]);
        }
    }

    // epilogue: c-frag rows gr, gr+8; cols 2ctg, 2ctg+1
#pragma unroll
    for (int mi = 0; mi < 4; mi++) {
        int r0 = bm + wm * 64 + mi * 16 + gr;
#pragma unroll
        for (int ni = 0; ni < 8; ni++) {
            int c0 = bn + wn * 64 + ni * 8 + 2 * ctg;
            if (HALF_OUT) {
                __half* C = (__half*)Cout;
                __half2 v0 = __floats2half2_rn(acc[mi][ni][0], acc[mi][ni][1]);
                __half2 v1 = __floats2half2_rn(acc[mi][ni][2], acc[mi][ni][3]);
                *(__half2*)&C[(size_t)r0 * N + c0]       = v0;
                *(__half2*)&C[(size_t)(r0 + 8) * N + c0] = v1;
            } else {
                float* C = (float*)Cout;
                float bx = 0.f, by = 0.f;
                if (BIAS) { bx = bias[c0]; by = bias[c0 + 1]; }
                float2 v0 = make_float2(acc[mi][ni][0] + bx, acc[mi][ni][1] + by);
                float2 v1 = make_float2(acc[mi][ni][2] + bx, acc[mi][ni][3] + by);
                *(float2*)&C[(size_t)r0 * N + c0]       = v0;
                *(float2*)&C[(size_t)(r0 + 8) * N + c0] = v1;
            }
        }
    }
}

// ---------------------------------------------------------------------------
// Block-local causal attention, fp16 mma + ldmatrix (verbatim from R5/R7).
// grid = (H, T/128, B), 256 threads.
// ---------------------------------------------------------------------------
#define QPH 72
#define PPH 136
#define OFF_Q 0
#define OFF_K (128 * QPH)
#define OFF_P (2 * 128 * QPH)
#define OFF_RED_B ((OFF_P + 128 * PPH) * 2)
#define ATT_B (OFF_RED_B + 128 * 4 * 4)

__global__ __launch_bounds__(256, 1)
void attn_h(const __half* __restrict__ qkv, __half* __restrict__ outp)
{
    extern __shared__ __half smh[];
    const uint32_t sbA = smem_u32(smh);
    const int h = blockIdx.x, blk = blockIdx.y, b = blockIdx.z;
    const int token0 = b * T_ + blk * BS_;
    const __half* qp = qkv + (size_t)token0 * N_QKV + h * Dh_;
    const __half* kp = qp + C_;
    const __half* vp = qp + 2 * C_;

    const int tid = threadIdx.x, lane = tid & 31, wid = tid >> 5;
    const int wm = wid >> 2, wn = wid & 3, gr = lane >> 2, ctg = lane & 3;

    __half* Qs = smh + OFF_Q;
    __half* Ks = smh + OFF_K;
    __half* Vs = smh + OFF_Q;
    __half* Ps = smh + OFF_P;
    float*  red = (float*)((char*)smh + OFF_RED_B);

    const uint32_t uQ = sbA + OFF_Q * 2;
    const uint32_t uK = sbA + OFF_K * 2;
    const uint32_t uV = uQ;
    const uint32_t uP = sbA + OFF_P * 2;

    for (int i = tid; i < 1024; i += 256) {
        int r = i >> 3, c8 = (i & 7) << 3;
        *(uint4*)&Qs[r * QPH + c8] = *(const uint4*)(qp + (size_t)r * N_QKV + c8);
        *(uint4*)&Ks[r * QPH + c8] = *(const uint4*)(kp + (size_t)r * N_QKV + c8);
    }
    __syncthreads();

    const uint32_t aOffQ = (uint32_t)((wm * 64 + (lane & 15)) * QPH + ((lane >> 4) << 3)) * 2;
    const uint32_t bOffK = (uint32_t)((wn * 32 + ((lane & 16) >> 1) + (lane & 7)) * QPH
                                      + ((lane & 8) ? 8 : 0)) * 2;
    const uint32_t aOffP = (uint32_t)((wm * 64 + (lane & 15)) * PPH + ((lane >> 4) << 3)) * 2;
    const uint32_t bOffV = (uint32_t)(((lane & 7) + ((lane & 8) ? 8 : 0)) * QPH
                                      + wn * 16 + ((lane & 16) ? 8 : 0)) * 2;

    float acc[4][4][4] = {};
    const bool liveQK = (wn * 32 <= wm * 64 + 63);
    if (liveQK) {
#pragma unroll
        for (int kk = 0; kk < 4; ++kk) {
            const uint32_t kbB = (uint32_t)(kk * 16) * 2;
            uint32_t a[4][4], bfr[4][2];
#pragma unroll
            for (int mi = 0; mi < 4; ++mi)
                LDSM4(a[mi][0], a[mi][1], a[mi][2], a[mi][3],
                      uQ + aOffQ + (uint32_t)(mi * 16 * QPH) * 2 + kbB);
#pragma unroll
            for (int pn = 0; pn < 2; ++pn)
                LDSM4(bfr[2 * pn][0], bfr[2 * pn][1], bfr[2 * pn + 1][0], bfr[2 * pn + 1][1],
                      uK + bOffK + (uint32_t)(pn * 16 * QPH) * 2 + kbB);
#pragma unroll
            for (int mi = 0; mi < 4; ++mi)
#pragma unroll
                for (int ni = 0; ni < 4; ++ni)
                    mma_f16(acc[mi][ni], a[mi], bfr[ni]);
        }
    }

    float rsum[4][2];
#pragma unroll
    for (int mi = 0; mi < 4; ++mi) { rsum[mi][0] = 0.f; rsum[mi][1] = 0.f; }
#pragma unroll
    for (int mi = 0; mi < 4; ++mi)
#pragma unroll
        for (int ni = 0; ni < 4; ++ni)
#pragma unroll
            for (int e = 0; e < 4; ++e) {
                int row = wm * 64 + mi * 16 + gr + ((e >= 2) ? 8 : 0);
                int col = wn * 32 + ni * 8 + 2 * ctg + (e & 1);
                float v = (col <= row) ? __expf(acc[mi][ni][e] * 0.125f) : 0.f;
                acc[mi][ni][e] = v;
                rsum[mi][e >> 1] += v;
            }
#pragma unroll
    for (int mi = 0; mi < 4; ++mi)
#pragma unroll
        for (int hl = 0; hl < 2; ++hl) {
            float s = rsum[mi][hl];
            s += __shfl_xor_sync(0xffffffffu, s, 1);
            s += __shfl_xor_sync(0xffffffffu, s, 2);
            rsum[mi][hl] = s;
        }
    if (ctg == 0)
#pragma unroll
        for (int mi = 0; mi < 4; ++mi)
#pragma unroll
            for (int hl = 0; hl < 2; ++hl)
                red[(wm * 64 + mi * 16 + gr + hl * 8) * 4 + wn] = rsum[mi][hl];
    __syncthreads();

    for (int i = tid; i < 1024; i += 256) {
        int r = i >> 3, c8 = (i & 7) << 3;
        *(uint4*)&Vs[r * QPH + c8] = *(const uint4*)(vp + (size_t)r * N_QKV + c8);
    }

#pragma unroll
    for (int mi = 0; mi < 4; ++mi)
#pragma unroll
        for (int hl = 0; hl < 2; ++hl) {
            int row = wm * 64 + mi * 16 + gr + hl * 8;
            float ssum = red[row * 4 + 0] + red[row * 4 + 1]
                       + red[row * 4 + 2] + red[row * 4 + 3];
            float inv = __fdividef(1.f, ssum + 1e-6f);
#pragma unroll
            for (int ni = 0; ni < 4; ++ni) {
                __half2 pv = __floats2half2_rn(acc[mi][ni][hl * 2 + 0] * inv,
                                               acc[mi][ni][hl * 2 + 1] * inv);
                *(__half2*)&Ps[row * PPH + wn * 32 + ni * 8 + 2 * ctg] = pv;
            }
        }
    __syncthreads();

    float oa[4][2][4] = {};
#pragma unroll
    for (int kk = 0; kk < 8; ++kk) {
        const uint32_t kbP = (uint32_t)(kk * 16) * 2;
        uint32_t a[4][4], bfr[2][2];
#pragma unroll
        for (int mi = 0; mi < 4; ++mi)
            LDSM4(a[mi][0], a[mi][1], a[mi][2], a[mi][3],
                  uP + aOffP + (uint32_t)(mi * 16 * PPH) * 2 + kbP);
        LDSM4T(bfr[0][0], bfr[0][1], bfr[1][0], bfr[1][1],
               uV + bOffV + (uint32_t)(kk * 16 * QPH) * 2);
#pragma unroll
        for (int mi = 0; mi < 4; ++mi)
#pragma unroll
            for (int ni = 0; ni < 2; ++ni)
                mma_f16(oa[mi][ni], a[mi], bfr[ni]);
    }

    __half* op = outp + (size_t)token0 * C_ + h * Dh_;
#pragma unroll
    for (int mi = 0; mi < 4; ++mi) {
        int r0 = wm * 64 + mi * 16 + gr;
#pragma unroll
        for (int ni = 0; ni < 2; ++ni) {
            int c0 = wn * 16 + ni * 8 + 2 * ctg;
            __half2 v0 = __floats2half2_rn(oa[mi][ni][0], oa[mi][ni][1]);
            __half2 v1 = __floats2half2_rn(oa[mi][ni][2], oa[mi][ni][3]);
            *(__half2*)&op[(size_t)r0 * C_ + c0]       = v0;
            *(__half2*)&op[(size_t)(r0 + 8) * C_ + c0] = v1;
        }
    }
}

// ---------------------------------------------------------------------------
extern "C" void kernel_launch(void* const* d_in, const int* in_sizes, int n_in,
                              void* d_out, int out_size)
{
    const float* x      = (const float*)d_in[0];
    const float* W_qkv  = (const float*)d_in[1];
    const float* W_proj = (const float*)d_in[2];
    const float* b_proj = (const float*)d_in[3];
    float* out = (float*)d_out;

    __half *qkvh, *attnh, *xh, *WqkvT, *WprojT;
    cudaGetSymbolAddress((void**)&qkvh,   g_qkvh);
    cudaGetSymbolAddress((void**)&attnh,  g_attnh);
    cudaGetSymbolAddress((void**)&xh,     g_xh);
    cudaGetSymbolAddress((void**)&WqkvT,  g_WqkvT);
    cudaGetSymbolAddress((void**)&WprojT, g_WprojT);

    static bool attr_set = false;
    if (!attr_set) {
        cudaFuncSetAttribute((const void*)gemm_h<false, true>,
                             cudaFuncAttributeMaxDynamicSharedMemorySize, GSMEM_B);
        cudaFuncSetAttribute((const void*)gemm_h<true, false>,
                             cudaFuncAttributeMaxDynamicSharedMemorySize, GSMEM_B);
        cudaFuncSetAttribute((const void*)attn_h,
                             cudaFuncAttributeMaxDynamicSharedMemorySize, ATT_B);
        attr_set = true;
    }

    // 0) fp16 conversions
    cvt_f2h<<<(M_TOK * C_ / 4 + 255) / 256, 256>>>((const float4*)x, (uint2*)xh,
                                                   M_TOK * C_ / 4);
    transpose_cvt<<<dim3(N_QKV / 32, KDIM / 32), dim3(32, 8)>>>(W_qkv, WqkvT, KDIM, N_QKV);
    transpose_cvt<<<dim3(C_ / 32, KDIM / 32), dim3(32, 8)>>>(W_proj, WprojT, KDIM, C_);

    // 1) qkv = x @ W_qkv  (fp16 mma, fp16 out)
    gemm_h<false, true><<<dim3(N_QKV / 128, M_TOK / 128), 128, GSMEM_B>>>(
        xh, WqkvT, nullptr, qkvh, N_QKV);

    // 2) block-local causal attention (fp16 mma)
    attn_h<<<dim3(H_, T_ / BS_, B_), 256, ATT_B>>>(qkvh, attnh);

    // 3) out = attn @ W_proj + b_proj (fp16 mma, fp32 out)
    gemm_h<true, false><<<dim3(C_ / 128, M_TOK / 128), 128, GSMEM_B>>>(
        attnh, WprojT, b_proj, out, C_);
}

// round 9
// speedup vs baseline: 1.4822x; 1.2003x over previous
#include <cuda_runtime.h>
#include <cuda_fp16.h>
#include <cstdint>

// Problem constants (B=4, T=4096, C=1024, H=16, D=64, BLOCK=128)
#define B_    4
#define T_    4096
#define C_    1024
#define H_    16
#define Dh_   64
#define BS_   128
#define M_TOK 16384
#define N_QKV 3072
#define KDIM  1024

// Scratch (allocation-free rule: __device__ globals)
__device__ __half g_qkvh  [(size_t)M_TOK * N_QKV];  // 96 MiB
__device__ __half g_attnh [(size_t)M_TOK * C_];     // 32 MiB
__device__ __half g_xh    [(size_t)M_TOK * C_];     // 32 MiB
__device__ __half g_WqkvT [(size_t)N_QKV * KDIM];   // 6 MiB  [N][K]
__device__ __half g_WprojT[(size_t)C_ * KDIM];      // 2 MiB  [N][K]

// ---------------------------------------------------------------------------
// helpers
// ---------------------------------------------------------------------------
__device__ __forceinline__ uint32_t smem_u32(const void* p) {
    uint32_t a;
    asm("{ .reg .u64 t; cvta.to.shared.u64 t, %1; cvt.u32.u64 %0, t; }" : "=r"(a) : "l"(p));
    return a;
}
// D += A*B, m16n8k16 f16 inputs, f32 accum
__device__ __forceinline__ void mma_f16(float* d, const uint32_t* a, const uint32_t* b) {
    asm volatile(
        "mma.sync.aligned.m16n8k16.row.col.f32.f16.f16.f32 "
        "{%0,%1,%2,%3}, {%4,%5,%6,%7}, {%8,%9}, {%0,%1,%2,%3};"
        : "+f"(d[0]), "+f"(d[1]), "+f"(d[2]), "+f"(d[3])
        : "r"(a[0]), "r"(a[1]), "r"(a[2]), "r"(a[3]), "r"(b[0]), "r"(b[1]));
}
#define LDSM4(r0, r1, r2, r3, addr) \
    asm volatile("ldmatrix.sync.aligned.m8n8.x4.shared.b16 {%0,%1,%2,%3}, [%4];" \
                 : "=r"(r0), "=r"(r1), "=r"(r2), "=r"(r3) : "r"(addr))
#define LDSM4T(r0, r1, r2, r3, addr) \
    asm volatile("ldmatrix.sync.aligned.m8n8.x4.trans.shared.b16 {%0,%1,%2,%3}, [%4];" \
                 : "=r"(r0), "=r"(r1), "=r"(r2), "=r"(r3) : "r"(addr))
#define CP16(dst, src) \
    asm volatile("cp.async.cg.shared.global [%0], [%1], 16;" :: "r"(dst), "l"(src))
#define CP_COMMIT() asm volatile("cp.async.commit_group;")
#define CP_WAIT1()  asm volatile("cp.async.wait_group 1;")

// ---------------------------------------------------------------------------
// conversion kernels
// ---------------------------------------------------------------------------
__global__ void cvt_f2h(const float4* __restrict__ in, uint2* __restrict__ out, int n4) {
    int i = blockIdx.x * blockDim.x + threadIdx.x;
    if (i < n4) {
        float4 v = in[i];
        __half2 h0 = __floats2half2_rn(v.x, v.y);
        __half2 h1 = __floats2half2_rn(v.z, v.w);
        out[i] = make_uint2(*(uint32_t*)&h0, *(uint32_t*)&h1);
    }
}
// in fp32 [R][Cc] -> out half [Cc][R]
__global__ void transpose_cvt(const float* __restrict__ in, __half* __restrict__ out,
                              int R, int Cc)
{
    __shared__ float t[32][33];
    int x = blockIdx.x * 32 + threadIdx.x;
    int y = blockIdx.y * 32 + threadIdx.y;
#pragma unroll
    for (int j = 0; j < 32; j += 8)
        t[threadIdx.y + j][threadIdx.x] = in[(size_t)(y + j) * Cc + x];
    __syncthreads();
    int x2 = blockIdx.y * 32 + threadIdx.x;
    int y2 = blockIdx.x * 32 + threadIdx.y;
#pragma unroll
    for (int j = 0; j < 32; j += 8)
        out[(size_t)(y2 + j) * R + x2] = __float2half(t[threadIdx.x][threadIdx.y + j]);
}

// ---------------------------------------------------------------------------
// fp16 mma GEMM (unchanged from R8): 128x128 CTA tiles, BK=64, 3-stage
// cp.async, 4 warps (2x2), 64x64 warp tile, ldmatrix, XOR-swizzled smem.
// ---------------------------------------------------------------------------
#define ROWB     128
#define ASTG_B   (128 * ROWB)
#define STG_B    (2 * ASTG_B)
#define GSMEM_B  (3 * STG_B)

__device__ __forceinline__ uint32_t swz(uint32_t row, uint32_t g) {
    return row * ROWB + (((g ^ (row & 7)) & 7) << 4);
}

template <bool BIAS, bool HALF_OUT>
__global__ __launch_bounds__(128, 2)
void gemm_h(const __half* __restrict__ A, const __half* __restrict__ Bt,
            const float* __restrict__ bias, void* __restrict__ Cout, int N)
{
    extern __shared__ __half smh[];
    const uint32_t sb = smem_u32(smh);
    const int tid = threadIdx.x, lane = tid & 31, wid = tid >> 5;
    const int wm = wid >> 1, wn = wid & 1, gr = lane >> 2, ctg = lane & 3;
    const int bm = blockIdx.y * 128, bn = blockIdx.x * 128;

    auto load_tile = [&](int s, int k0) {
        uint32_t sA = sb + (uint32_t)(s * STG_B);
        uint32_t sB = sA + ASTG_B;
#pragma unroll
        for (int i = 0; i < 8; i++) {
            int ch = tid + i * 128;
            uint32_t r = ch >> 3, g = ch & 7;
            CP16(sA + swz(r, g), A + (size_t)(bm + r) * KDIM + k0 + g * 8);
        }
#pragma unroll
        for (int i = 0; i < 8; i++) {
            int ch = tid + i * 128;
            uint32_t r = ch >> 3, g = ch & 7;
            CP16(sB + swz(r, g), Bt + (size_t)(bn + r) * KDIM + k0 + g * 8);
        }
    };

    const uint32_t rA  = (uint32_t)(wm * 64 + (lane & 15));
    const uint32_t gA0 = (uint32_t)(lane >> 4);
    const uint32_t rB  = (uint32_t)(wn * 64 + ((lane & 16) >> 1) + (lane & 7));
    const uint32_t gB0 = (uint32_t)((lane & 8) >> 3);

    load_tile(0, 0);  CP_COMMIT();
    load_tile(1, 64); CP_COMMIT();

    float acc[4][8][4] = {};

    for (int it = 0; it < 16; ++it) {
        const int s = it % 3;
        CP_WAIT1();
        __syncthreads();
        if (it + 2 < 16) load_tile((it + 2) % 3, (it + 2) * 64);
        CP_COMMIT();

        const uint32_t sA = sb + (uint32_t)(s * STG_B);
        const uint32_t sB = sA + ASTG_B;
#pragma unroll
        for (int kk = 0; kk < 4; ++kk) {
            const uint32_t gA = 2 * kk + gA0;
            const uint32_t gB = 2 * kk + gB0;
            uint32_t a[4][4], bfr[8][2];
#pragma unroll
            for (int mi = 0; mi < 4; ++mi)
                LDSM4(a[mi][0], a[mi][1], a[mi][2], a[mi][3],
                      sA + swz(rA + mi * 16, gA));
#pragma unroll
            for (int pn = 0; pn < 4; ++pn)
                LDSM4(bfr[2 * pn][0], bfr[2 * pn][1], bfr[2 * pn + 1][0], bfr[2 * pn + 1][1],
                      sB + swz(rB + pn * 16, gB));
#pragma unroll
            for (int mi = 0; mi < 4; ++mi)
#pragma unroll
                for (int ni = 0; ni < 8; ++ni)
                    mma_f16(acc[mi][ni], a[mi], bfr[ni]);
        }
    }

#pragma unroll
    for (int mi = 0; mi < 4; mi++) {
        int r0 = bm + wm * 64 + mi * 16 + gr;
#pragma unroll
        for (int ni = 0; ni < 8; ni++) {
            int c0 = bn + wn * 64 + ni * 8 + 2 * ctg;
            if (HALF_OUT) {
                __half* C = (__half*)Cout;
                __half2 v0 = __floats2half2_rn(acc[mi][ni][0], acc[mi][ni][1]);
                __half2 v1 = __floats2half2_rn(acc[mi][ni][2], acc[mi][ni][3]);
                *(__half2*)&C[(size_t)r0 * N + c0]       = v0;
                *(__half2*)&C[(size_t)(r0 + 8) * N + c0] = v1;
            } else {
                float* C = (float*)Cout;
                float bx = 0.f, by = 0.f;
                if (BIAS) { bx = bias[c0]; by = bias[c0 + 1]; }
                float2 v0 = make_float2(acc[mi][ni][0] + bx, acc[mi][ni][1] + by);
                float2 v1 = make_float2(acc[mi][ni][2] + bx, acc[mi][ni][3] + by);
                *(float2*)&C[(size_t)r0 * N + c0]       = v0;
                *(float2*)&C[(size_t)(r0 + 8) * N + c0] = v1;
            }
        }
    }
}

// ---------------------------------------------------------------------------
// Block-local causal attention, streaming P·V with P in registers.
// grid = (H, T/128, B), 256 threads (8 warps; warp w owns query rows 16w..16w+15).
// Per warp: loop key-chunks kt = 0..w (causal trim). For each chunk:
//   S-frags (8 HMMA) -> mask/exp in regs -> rowsum accumulates ->
//   c-frag reinterpreted as A-frag -> P·V (8 HMMA). Scale O by 1/sum at end.
// ONE __syncthreads total. No P smem, no reduction smem.
// ---------------------------------------------------------------------------
#define QPH 72                               // pitch (halves), conflict-free LDSM
#define AOFF_Q 0
#define AOFF_K (128 * QPH)
#define AOFF_V (2 * 128 * QPH)
#define ATT2_B (3 * 128 * QPH * 2)           // 55296 bytes

__global__ __launch_bounds__(256)
void attn_h(const __half* __restrict__ qkv, __half* __restrict__ outp)
{
    extern __shared__ __half smh[];
    const uint32_t sbA = smem_u32(smh);
    const int h = blockIdx.x, blk = blockIdx.y, b = blockIdx.z;
    const int token0 = b * T_ + blk * BS_;
    const __half* qp = qkv + (size_t)token0 * N_QKV + h * Dh_;
    const __half* kp = qp + C_;
    const __half* vp = qp + 2 * C_;

    const int tid = threadIdx.x, lane = tid & 31, wid = tid >> 5;
    const int gr = lane >> 2, ctg = lane & 3;

    __half* Qs = smh + AOFF_Q;
    __half* Ks = smh + AOFF_K;
    __half* Vs = smh + AOFF_V;
    const uint32_t uQ = sbA + AOFF_Q * 2;
    const uint32_t uK = sbA + AOFF_K * 2;
    const uint32_t uV = sbA + AOFF_V * 2;

    // load Q, K, V (8 halves per chunk, 4 iters each)
    for (int i = tid; i < 1024; i += 256) {
        int r = i >> 3, c8 = (i & 7) << 3;
        *(uint4*)&Qs[r * QPH + c8] = *(const uint4*)(qp + (size_t)r * N_QKV + c8);
        *(uint4*)&Ks[r * QPH + c8] = *(const uint4*)(kp + (size_t)r * N_QKV + c8);
        *(uint4*)&Vs[r * QPH + c8] = *(const uint4*)(vp + (size_t)r * N_QKV + c8);
    }
    __syncthreads();

    // lane bases
    const uint32_t aOffQ = (uint32_t)((wid * 16 + (lane & 15)) * QPH + ((lane >> 4) << 3)) * 2;
    const uint32_t bOffK = (uint32_t)((((lane & 16) >> 1) + (lane & 7)) * QPH
                                      + ((lane & 8) ? 8 : 0)) * 2;
    const uint32_t bOffV = (uint32_t)(((lane & 7) + ((lane & 8) ? 8 : 0)) * QPH
                                      + ((lane & 16) ? 8 : 0)) * 2;

    float oa[8][4] = {};                // O acc: 8 n8-tiles over d=64
    float rs0 = 0.f, rs1 = 0.f;         // row sums (rows gr, gr+8)

    for (int kt = 0; kt <= wid; ++kt) {
        // ---- S chunk: rows 16wid.., keys 16kt..16kt+15 ----
        float sa[2][4] = {};
#pragma unroll
        for (int kk = 0; kk < 4; ++kk) {
            uint32_t afr[4], b0, b1, b2, b3;
            LDSM4(afr[0], afr[1], afr[2], afr[3], uQ + aOffQ + kk * 32);
            LDSM4(b0, b1, b2, b3,
                  uK + bOffK + (uint32_t)(kt * 16 * QPH) * 2 + kk * 32);
            uint32_t bf0[2] = {b0, b1}, bf1[2] = {b2, b3};
            mma_f16(sa[0], afr, bf0);
            mma_f16(sa[1], afr, bf1);
        }

        // ---- mask + exp + rowsum ----
        const bool diag = (kt == wid);
#pragma unroll
        for (int j = 0; j < 2; ++j)
#pragma unroll
            for (int e = 0; e < 4; ++e) {
                int col = j * 8 + 2 * ctg + (e & 1);                    // within chunk
                int rowi = gr + ((e >= 2) ? 8 : 0);                     // within warp rows
                float v = (!diag || (col <= rowi + 0 * kt)) ?           // diag: col<=row
                          __expf(sa[j][e] * 0.125f) : 0.f;
                // note: diag chunk shares base 16*kt == 16*wid, so compare within-16 idx
                sa[j][e] = v;
                if (e < 2) rs0 += v; else rs1 += v;
            }

        // ---- P c-frag -> A-frag ----
        uint32_t pa[4];
        {
            __half2 t0 = __floats2half2_rn(sa[0][0], sa[0][1]);
            __half2 t1 = __floats2half2_rn(sa[0][2], sa[0][3]);
            __half2 t2 = __floats2half2_rn(sa[1][0], sa[1][1]);
            __half2 t3 = __floats2half2_rn(sa[1][2], sa[1][3]);
            pa[0] = *(uint32_t*)&t0;  pa[1] = *(uint32_t*)&t1;
            pa[2] = *(uint32_t*)&t2;  pa[3] = *(uint32_t*)&t3;
        }

        // ---- P·V for this chunk (V rows = keys 16kt..16kt+15) ----
#pragma unroll
        for (int j2 = 0; j2 < 4; ++j2) {
            uint32_t v0, v1, v2, v3;
            LDSM4T(v0, v1, v2, v3,
                   uV + bOffV + (uint32_t)(kt * 16 * QPH) * 2 + (uint32_t)(j2 * 16) * 2);
            uint32_t bf0[2] = {v0, v1}, bf1[2] = {v2, v3};
            mma_f16(oa[2 * j2],     pa, bf0);
            mma_f16(oa[2 * j2 + 1], pa, bf1);
        }
    }

    // ---- finalize: reduce row sums over the 4 ctg lanes, scale, store ----
    {
        float s0 = rs0, s1 = rs1;
        s0 += __shfl_xor_sync(0xffffffffu, s0, 1);
        s0 += __shfl_xor_sync(0xffffffffu, s0, 2);
        s1 += __shfl_xor_sync(0xffffffffu, s1, 1);
        s1 += __shfl_xor_sync(0xffffffffu, s1, 2);
        float inv0 = __fdividef(1.f, s0 + 1e-6f);
        float inv1 = __fdividef(1.f, s1 + 1e-6f);

        __half* op = outp + (size_t)token0 * C_ + h * Dh_;
        int r0 = wid * 16 + gr;
#pragma unroll
        for (int jt = 0; jt < 8; ++jt) {
            int c0 = jt * 8 + 2 * ctg;
            __half2 v0 = __floats2half2_rn(oa[jt][0] * inv0, oa[jt][1] * inv0);
            __half2 v1 = __floats2half2_rn(oa[jt][2] * inv1, oa[jt][3] * inv1);
            *(__half2*)&op[(size_t)r0 * C_ + c0]       = v0;
            *(__half2*)&op[(size_t)(r0 + 8) * C_ + c0] = v1;
        }
    }
}

// ---------------------------------------------------------------------------
extern "C" void kernel_launch(void* const* d_in, const int* in_sizes, int n_in,
                              void* d_out, int out_size)
{
    const float* x      = (const float*)d_in[0];
    const float* W_qkv  = (const float*)d_in[1];
    const float* W_proj = (const float*)d_in[2];
    const float* b_proj = (const float*)d_in[3];
    float* out = (float*)d_out;

    __half *qkvh, *attnh, *xh, *WqkvT, *WprojT;
    cudaGetSymbolAddress((void**)&qkvh,   g_qkvh);
    cudaGetSymbolAddress((void**)&attnh,  g_attnh);
    cudaGetSymbolAddress((void**)&xh,     g_xh);
    cudaGetSymbolAddress((void**)&WqkvT,  g_WqkvT);
    cudaGetSymbolAddress((void**)&WprojT, g_WprojT);

    static bool attr_set = false;
    if (!attr_set) {
        cudaFuncSetAttribute((const void*)gemm_h<false, true>,
                             cudaFuncAttributeMaxDynamicSharedMemorySize, GSMEM_B);
        cudaFuncSetAttribute((const void*)gemm_h<true, false>,
                             cudaFuncAttributeMaxDynamicSharedMemorySize, GSMEM_B);
        cudaFuncSetAttribute((const void*)attn_h,
                             cudaFuncAttributeMaxDynamicSharedMemorySize, ATT2_B);
        attr_set = true;
    }

    // 0) fp16 conversions
    cvt_f2h<<<(M_TOK * C_ / 4 + 255) / 256, 256>>>((const float4*)x, (uint2*)xh,
                                                   M_TOK * C_ / 4);
    transpose_cvt<<<dim3(N_QKV / 32, KDIM / 32), dim3(32, 8)>>>(W_qkv, WqkvT, KDIM, N_QKV);
    transpose_cvt<<<dim3(C_ / 32, KDIM / 32), dim3(32, 8)>>>(W_proj, WprojT, KDIM, C_);

    // 1) qkv = x @ W_qkv  (fp16 mma, fp16 out)
    gemm_h<false, true><<<dim3(N_QKV / 128, M_TOK / 128), 128, GSMEM_B>>>(
        xh, WqkvT, nullptr, qkvh, N_QKV);

    // 2) block-local causal attention (fp16 mma, streaming P·V)
    attn_h<<<dim3(H_, T_ / BS_, B_), 256, ATT2_B>>>(qkvh, attnh);

    // 3) out = attn @ W_proj + b_proj (fp16 mma, fp32 out)
    gemm_h<true, false><<<dim3(C_ / 128, M_TOK / 128), 128, GSMEM_B>>>(
        attnh, WprojT, b_proj, out, C_);
}